// round 12
// baseline (speedup 1.0000x reference)
#include <cuda_runtime.h>
#include <cuda_fp16.h>
#include <cstdint>
#include <cstddef>

// ---------------------------------------------------------------------------
// MinGRU: single-pass fp16 GEMM (mma.sync.m16n8k16), CTA tile 128x256,
// warp tile 64x64 (MMA:LDSM ratio 4.0 vs 2.67 at 64x32) to attack the
// measured 66%-of-peak issue efficiency. fp16 z/h~ intermediates + segmented
// affine scan (both measured at predicted rates in R11).
// ---------------------------------------------------------------------------

#define B_DIM 16
#define T_DIM 2048
#define D_DIM 1024
#define H_DIM 1024
#define M_TOT (B_DIM * T_DIM)   // 32768
#define N_TOT (2 * H_DIM)       // 2048
#define K_TOT D_DIM             // 1024

#define KC      64              // K elems per stage (128B fp16 rows)
#define NSTG    3
#define NCHUNK  (K_TOT / KC)    // 16
#define TILE_A  (128 * 128)     // 16KB  (128 rows x 128B)
#define TILE_BB (256 * 128)     // 32KB  (256 rows x 128B)
#define STG_B   (TILE_A + TILE_BB)  // 48KB
#define SMEM_TOTAL (NSTG * STG_B)   // 147456 -> 1 CTA/SM

#define SEG     16              // scan segments
#define SEGLEN  (T_DIM / SEG)   // 128
#define NLANES  (B_DIM * H_DIM) // 16384

// ---------------- scratch (static device memory; no allocation) -------------
__device__ __align__(256) __half g_xh[(size_t)M_TOT * K_TOT];   // 64MB
__device__ __align__(256) __half g_wh[(size_t)N_TOT * K_TOT];   // 4MB
__device__ __align__(256) __half g_zb[(size_t)M_TOT * H_DIM];   // gates (fp16)
__device__ __align__(256) __half g_hb[(size_t)M_TOT * H_DIM];   // cands (fp16)
__device__ __align__(256) float g_P[SEG][NLANES];               // seg prod
__device__ __align__(256) float g_Q[SEG][NLANES];               // seg offset

// ---------------- PTX helpers ----------------------------------------------
__device__ __forceinline__ uint32_t s2u(const void* p) {
    return (uint32_t)__cvta_generic_to_shared(p);
}
__device__ __forceinline__ void cp_async16(uint32_t dst, const void* src) {
    asm volatile("cp.async.cg.shared.global [%0], [%1], 16;" :: "r"(dst), "l"(src) : "memory");
}
__device__ __forceinline__ void cp_commit() {
    asm volatile("cp.async.commit_group;" ::: "memory");
}
__device__ __forceinline__ void cp_wait1() {
    asm volatile("cp.async.wait_group 1;" ::: "memory");
}
__device__ __forceinline__ void ldsm4(uint32_t* r, uint32_t addr) {
    asm volatile("ldmatrix.sync.aligned.m8n8.x4.shared.b16 {%0,%1,%2,%3}, [%4];"
                 : "=r"(r[0]), "=r"(r[1]), "=r"(r[2]), "=r"(r[3]) : "r"(addr));
}
__device__ __forceinline__ void mma16816(float* d, const uint32_t* a, uint32_t b0, uint32_t b1) {
    asm volatile("mma.sync.aligned.m16n8k16.row.col.f32.f16.f16.f32 "
                 "{%0,%1,%2,%3}, {%4,%5,%6,%7}, {%8,%9}, {%0,%1,%2,%3};"
                 : "+f"(d[0]), "+f"(d[1]), "+f"(d[2]), "+f"(d[3])
                 : "r"(a[0]), "r"(a[1]), "r"(a[2]), "r"(a[3]), "r"(b0), "r"(b1));
}

// ---------------- convert kernels -------------------------------------------
__global__ void conv_x_k(const float* __restrict__ x) {
    size_t i = (size_t)blockIdx.x * blockDim.x + threadIdx.x;  // group of 8 elems
    size_t e = i * 8;
    const float4* src = (const float4*)(x + e);
    float4 a = src[0], b = src[1];
    float f[8] = {a.x, a.y, a.z, a.w, b.x, b.y, b.z, b.w};
    union { __half h[8]; uint4 u; } H;
#pragma unroll
    for (int j = 0; j < 8; j++) H.h[j] = __float2half_rn(f[j]);
    ((uint4*)g_xh)[i] = H.u;
}

__global__ void conv_w_k(const float* __restrict__ Wz, const float* __restrict__ Wh) {
    size_t i = (size_t)blockIdx.x * blockDim.x + threadIdx.x;
    size_t e = i * 8;
    int row = (int)(e >> 10);
    int k = (int)(e & 1023);
    const float* srcp = (row < H_DIM) ? (Wz + (size_t)row * D_DIM + k)
                                      : (Wh + (size_t)(row - H_DIM) * D_DIM + k);
    float4 a = ((const float4*)srcp)[0], b = ((const float4*)srcp)[1];
    float f[8] = {a.x, a.y, a.z, a.w, b.x, b.y, b.z, b.w};
    union { __half h[8]; uint4 u; } H;
#pragma unroll
    for (int j = 0; j < 8; j++) H.h[j] = __float2half_rn(f[j]);
    ((uint4*)g_wh)[i] = H.u;
}

// ---------------- GEMM ------------------------------------------------------
// Stage: A (128 rows) then B (256 rows), each row 128B, xor-swizzled.
__device__ __forceinline__ void load_stage(uint32_t dst, int m0, int n0, int k0, int tid) {
    const char* pA = (const char*)(g_xh + (size_t)m0 * K_TOT + k0);
    const char* pB = (const char*)(g_wh + (size_t)n0 * K_TOT + k0);
#pragma unroll
    for (int i = 0; i < 4; i++) {          // A: 128 rows x 8 granules = 1024
        int gid = i * 256 + tid;
        int r = gid >> 3;
        int cb = gid & 7;
        uint32_t bo = (uint32_t)(r * 128 + cb * 16);
        uint32_t sw = bo ^ ((bo >> 3) & 0x70);
        cp_async16(dst + sw, pA + (size_t)r * (K_TOT * 2) + cb * 16);
    }
#pragma unroll
    for (int i = 0; i < 8; i++) {          // B: 256 rows x 8 granules = 2048
        int gid = i * 256 + tid;
        int r = gid >> 3;
        int cb = gid & 7;
        uint32_t bo = (uint32_t)(r * 128 + cb * 16);
        uint32_t sw = bo ^ ((bo >> 3) & 0x70);
        cp_async16(dst + TILE_A + sw, pB + (size_t)r * (K_TOT * 2) + cb * 16);
    }
}

__global__ void __launch_bounds__(256, 1)
gemm_k(const float* __restrict__ bz, const float* __restrict__ bh) {
    extern __shared__ __align__(1024) char smem[];
    const uint32_t sb = s2u(smem);
    const int tid = threadIdx.x;
    const int wid = tid >> 5, lane = tid & 31;
    const int nt = blockIdx.x;   // 0..7  (256-wide N tiles)
    const int mt = blockIdx.y;   // 0..255
    const int m0 = mt * 128, n0 = nt * 256;

    const int warp_m = wid & 1;  // 2 -> m 64
    const int warp_n = wid >> 1; // 4 -> n 64

    const int rowA = lane & 15, kqA = lane >> 4;
    const int rowB = (lane & 7) + ((lane >> 4) << 3);
    const int kqB = (lane >> 3) & 1;
    const uint32_t xorA = (uint32_t)((rowA & 7) << 4);
    const uint32_t xorB = (uint32_t)((rowB & 7) << 4);
    uint32_t rbyteA[4], rbyteB[4];
#pragma unroll
    for (int im = 0; im < 4; im++)
        rbyteA[im] = (uint32_t)((warp_m * 64 + im * 16 + rowA) * 128);
#pragma unroll
    for (int ib = 0; ib < 4; ib++)
        rbyteB[ib] = (uint32_t)((warp_n * 64 + ib * 16 + rowB) * 128);

    float acc[4][8][4];
#pragma unroll
    for (int im = 0; im < 4; im++)
#pragma unroll
        for (int in = 0; in < 8; in++)
#pragma unroll
            for (int q = 0; q < 4; q++) acc[im][in][q] = 0.0f;

    // prologue: stages 0,1
    load_stage(sb, m0, n0, 0, tid); cp_commit();
    load_stage(sb + STG_B, m0, n0, KC, tid); cp_commit();

    for (int c = 0; c < NCHUNK; c++) {
        cp_wait1();
        __syncthreads();
        const uint32_t baseA = sb + (c % NSTG) * STG_B;
        const uint32_t baseB = baseA + TILE_A;
#pragma unroll
        for (int kk = 0; kk < 4; kk++) {
            const uint32_t offA = ((uint32_t)(kk * 32 + kqA * 16)) ^ xorA;
            const uint32_t offB = ((uint32_t)(kk * 32 + kqB * 16)) ^ xorB;
            uint32_t ra[4][4], rb[4][4];
#pragma unroll
            for (int im = 0; im < 4; im++) ldsm4(ra[im], baseA + rbyteA[im] + offA);
#pragma unroll
            for (int ib = 0; ib < 4; ib++) ldsm4(rb[ib], baseB + rbyteB[ib] + offB);
#pragma unroll
            for (int im = 0; im < 4; im++)
#pragma unroll
                for (int in = 0; in < 8; in++)
                    mma16816(acc[im][in], ra[im], rb[in >> 1][(in & 1) * 2], rb[in >> 1][(in & 1) * 2 + 1]);
        }
        __syncthreads();
        if (c + 2 < NCHUNK) {
            load_stage(sb + ((c + 2) % NSTG) * STG_B, m0, n0, (c + 2) * KC, tid);
        }
        cp_commit();
    }

    // epilogue: bias + (sigmoid), store fp16 -> g_zb / g_hb
    const bool zt = (nt < 4);
    const float* bias = zt ? bz : bh;
    __half* buf = zt ? g_zb : g_hb;
    const int nbase = n0 - (zt ? 0 : 1024);

#pragma unroll
    for (int in = 0; in < 8; in++) {
        const int col = nbase + warp_n * 64 + in * 8 + (lane & 3) * 2;  // even
        const float b0 = __ldg(&bias[col]);
        const float b1 = __ldg(&bias[col + 1]);
#pragma unroll
        for (int im = 0; im < 4; im++) {
            const int row = m0 + warp_m * 64 + im * 16 + (lane >> 2);
            float v0 = acc[im][in][0] + b0;
            float v1 = acc[im][in][1] + b1;
            float v2 = acc[im][in][2] + b0;
            float v3 = acc[im][in][3] + b1;
            if (zt) {
                v0 = 1.0f / (1.0f + __expf(-v0));
                v1 = 1.0f / (1.0f + __expf(-v1));
                v2 = 1.0f / (1.0f + __expf(-v2));
                v3 = 1.0f / (1.0f + __expf(-v3));
            }
            *(__half2*)(buf + (size_t)row * H_DIM + col) =
                __halves2half2(__float2half_rn(v0), __float2half_rn(v1));
            *(__half2*)(buf + (size_t)(row + 8) * H_DIM + col) =
                __halves2half2(__float2half_rn(v2), __float2half_rn(v3));
        }
    }
}

// ---------------- scan: segment summaries then replay ------------------------
__global__ void scan_sum_k() {
    const int idx = blockIdx.x * blockDim.x + threadIdx.x;  // (SEG-1)*8192
    const int seg = idx >> 13;            // 0..14
    const int pr = idx & 8191;
    const int lane0 = pr * 2;
    const int b = lane0 >> 10;
    const int h = lane0 & 1023;
    const size_t base = ((size_t)b * T_DIM + seg * SEGLEN) * H_DIM + h;
    const __half* zp = g_zb + base;
    const __half* hp = g_hb + base;
    float P0 = 1.0f, Q0 = 0.0f, P1 = 1.0f, Q1 = 0.0f;
#pragma unroll 8
    for (int t = 0; t < SEGLEN; t++) {
        const float2 z = __half22float2(*(const __half2*)(zp + (size_t)t * H_DIM));
        const float2 ht = __half22float2(*(const __half2*)(hp + (size_t)t * H_DIM));
        const float a0 = 1.0f - z.x, a1 = 1.0f - z.y;
        P0 *= a0; Q0 = fmaf(a0, Q0, z.x * ht.x);
        P1 *= a1; Q1 = fmaf(a1, Q1, z.y * ht.y);
    }
    *(float2*)&g_P[seg][lane0] = make_float2(P0, P1);
    *(float2*)&g_Q[seg][lane0] = make_float2(Q0, Q1);
}

__global__ void scan_final_k(const float* __restrict__ h0, float* __restrict__ out) {
    const int idx = blockIdx.x * blockDim.x + threadIdx.x;  // SEG*8192
    const int seg = idx >> 13;            // 0..15
    const int pr = idx & 8191;
    const int lane0 = pr * 2;
    const int b = lane0 >> 10;
    const int h = lane0 & 1023;
    float2 hh = *(const float2*)(h0 + lane0);
    for (int s = 0; s < seg; s++) {
        const float2 P = *(const float2*)&g_P[s][lane0];
        const float2 Q = *(const float2*)&g_Q[s][lane0];
        hh.x = fmaf(P.x, hh.x, Q.x);
        hh.y = fmaf(P.y, hh.y, Q.y);
    }
    const size_t base = ((size_t)b * T_DIM + seg * SEGLEN) * H_DIM + h;
    const __half* zp = g_zb + base;
    const __half* hp = g_hb + base;
    float* op = out + base;
#pragma unroll 8
    for (int t = 0; t < SEGLEN; t++) {
        const float2 z = __half22float2(*(const __half2*)(zp + (size_t)t * H_DIM));
        const float2 ht = __half22float2(*(const __half2*)(hp + (size_t)t * H_DIM));
        hh.x = fmaf(z.x, ht.x - hh.x, hh.x);
        hh.y = fmaf(z.y, ht.y - hh.y, hh.y);
        *(float2*)(op + (size_t)t * H_DIM) = hh;
    }
}

// ---------------- launch -----------------------------------------------------
extern "C" void kernel_launch(void* const* d_in, const int* in_sizes, int n_in,
                              void* d_out, int out_size) {
    const float* x  = (const float*)d_in[0];
    const float* h0 = (const float*)d_in[1];
    const float* Wz = (const float*)d_in[2];
    const float* bz = (const float*)d_in[3];
    const float* Wh = (const float*)d_in[4];
    const float* bh = (const float*)d_in[5];
    float* out = (float*)d_out;

    cudaFuncSetAttribute(gemm_k, cudaFuncAttributeMaxDynamicSharedMemorySize, SMEM_TOTAL);

    conv_x_k<<<16384, 256>>>(x);
    conv_w_k<<<1024, 256>>>(Wz, Wh);
    // n fastest: 8 n-tiles per m-tile run concurrently; A+B stay L2-resident
    gemm_k<<<dim3(8, 256, 1), 256, SMEM_TOTAL>>>(bz, bh);
    scan_sum_k<<<480, 256>>>();
    scan_final_k<<<512, 256>>>(h0, out);
}

// round 15
// speedup vs baseline: 1.1290x; 1.1290x over previous
#include <cuda_runtime.h>
#include <cuda_fp16.h>
#include <cstdint>
#include <cstddef>

// ---------------------------------------------------------------------------
// MinGRU: single-pass fp16 GEMM (mma.sync.m16n8k16).
// R12 lesson: 128x256 tile @ 1 CTA/SM REGRESSED (sync/latency exposure).
// R13: CTA 128x128 with FOUR 64x64 warps (128 threads, 2 CTAs/SM):
// same traffic/intensity as R11 but MMA:LDSM 4.0 and cheap syncs, keeping
// co-residency. fp16 z/h~ intermediates + segmented affine scan (measured).
// ---------------------------------------------------------------------------

#define B_DIM 16
#define T_DIM 2048
#define D_DIM 1024
#define H_DIM 1024
#define M_TOT (B_DIM * T_DIM)   // 32768
#define N_TOT (2 * H_DIM)       // 2048
#define K_TOT D_DIM             // 1024

#define KC      64              // K elems per stage (128B fp16 rows)
#define NSTG    3
#define NCHUNK  (K_TOT / KC)    // 16
#define TILE_B  (128 * 128)     // 16KB per tile
#define STG_B   (2 * TILE_B)    // A + B = 32KB
#define SMEM_TOTAL (NSTG * STG_B)  // 98304 -> 2 CTAs/SM (128 thr each)

#define SEG     16              // scan segments
#define SEGLEN  (T_DIM / SEG)   // 128
#define NLANES  (B_DIM * H_DIM) // 16384

// ---------------- scratch (static device memory; no allocation) -------------
__device__ __align__(256) __half g_xh[(size_t)M_TOT * K_TOT];   // 64MB
__device__ __align__(256) __half g_wh[(size_t)N_TOT * K_TOT];   // 4MB
__device__ __align__(256) __half g_zb[(size_t)M_TOT * H_DIM];   // gates (fp16)
__device__ __align__(256) __half g_hb[(size_t)M_TOT * H_DIM];   // cands (fp16)
__device__ __align__(256) float g_P[SEG][NLANES];               // seg prod
__device__ __align__(256) float g_Q[SEG][NLANES];               // seg offset

// ---------------- PTX helpers ----------------------------------------------
__device__ __forceinline__ uint32_t s2u(const void* p) {
    return (uint32_t)__cvta_generic_to_shared(p);
}
__device__ __forceinline__ void cp_async16(uint32_t dst, const void* src) {
    asm volatile("cp.async.cg.shared.global [%0], [%1], 16;" :: "r"(dst), "l"(src) : "memory");
}
__device__ __forceinline__ void cp_commit() {
    asm volatile("cp.async.commit_group;" ::: "memory");
}
__device__ __forceinline__ void cp_wait1() {
    asm volatile("cp.async.wait_group 1;" ::: "memory");
}
__device__ __forceinline__ void ldsm4(uint32_t* r, uint32_t addr) {
    asm volatile("ldmatrix.sync.aligned.m8n8.x4.shared.b16 {%0,%1,%2,%3}, [%4];"
                 : "=r"(r[0]), "=r"(r[1]), "=r"(r[2]), "=r"(r[3]) : "r"(addr));
}
__device__ __forceinline__ void mma16816(float* d, const uint32_t* a, uint32_t b0, uint32_t b1) {
    asm volatile("mma.sync.aligned.m16n8k16.row.col.f32.f16.f16.f32 "
                 "{%0,%1,%2,%3}, {%4,%5,%6,%7}, {%8,%9}, {%0,%1,%2,%3};"
                 : "+f"(d[0]), "+f"(d[1]), "+f"(d[2]), "+f"(d[3])
                 : "r"(a[0]), "r"(a[1]), "r"(a[2]), "r"(a[3]), "r"(b0), "r"(b1));
}

// ---------------- convert kernels -------------------------------------------
__global__ void conv_x_k(const float* __restrict__ x) {
    size_t i = (size_t)blockIdx.x * blockDim.x + threadIdx.x;  // group of 8 elems
    size_t e = i * 8;
    const float4* src = (const float4*)(x + e);
    float4 a = src[0], b = src[1];
    float f[8] = {a.x, a.y, a.z, a.w, b.x, b.y, b.z, b.w};
    union { __half h[8]; uint4 u; } H;
#pragma unroll
    for (int j = 0; j < 8; j++) H.h[j] = __float2half_rn(f[j]);
    ((uint4*)g_xh)[i] = H.u;
}

__global__ void conv_w_k(const float* __restrict__ Wz, const float* __restrict__ Wh) {
    size_t i = (size_t)blockIdx.x * blockDim.x + threadIdx.x;
    size_t e = i * 8;
    int row = (int)(e >> 10);
    int k = (int)(e & 1023);
    const float* srcp = (row < H_DIM) ? (Wz + (size_t)row * D_DIM + k)
                                      : (Wh + (size_t)(row - H_DIM) * D_DIM + k);
    float4 a = ((const float4*)srcp)[0], b = ((const float4*)srcp)[1];
    float f[8] = {a.x, a.y, a.z, a.w, b.x, b.y, b.z, b.w};
    union { __half h[8]; uint4 u; } H;
#pragma unroll
    for (int j = 0; j < 8; j++) H.h[j] = __float2half_rn(f[j]);
    ((uint4*)g_wh)[i] = H.u;
}

// ---------------- GEMM ------------------------------------------------------
// 128 threads load A tile (128x64 fp16) + B tile: 2048 granules, 16/thread.
__device__ __forceinline__ void load_stage(uint32_t dst, int m0, int n0, int k0, int tid) {
    const char* pA = (const char*)(g_xh + (size_t)m0 * K_TOT + k0);
    const char* pB = (const char*)(g_wh + (size_t)n0 * K_TOT + k0);
#pragma unroll
    for (int i = 0; i < 8; i++) {
        int gid = i * 128 + tid;       // 0..1023
        int r = gid >> 3;              // row 0..127
        int cb = gid & 7;              // 16B granule
        uint32_t bo = (uint32_t)(r * 128 + cb * 16);
        uint32_t sw = bo ^ ((bo >> 3) & 0x70);
        size_t goff = (size_t)r * (K_TOT * 2) + cb * 16;
        cp_async16(dst + sw,          pA + goff);
        cp_async16(dst + TILE_B + sw, pB + goff);
    }
}

__global__ void __launch_bounds__(128, 2)
gemm_k(const float* __restrict__ bz, const float* __restrict__ bh) {
    extern __shared__ __align__(1024) char smem[];
    const uint32_t sb = s2u(smem);
    const int tid = threadIdx.x;
    const int wid = tid >> 5, lane = tid & 31;    // 4 warps
    const int nt = blockIdx.x;   // 0..15
    const int mt = blockIdx.y;   // 0..255
    const int m0 = mt * 128, n0 = nt * 128;

    const int warp_m = wid & 1;  // 2 -> m 64
    const int warp_n = wid >> 1; // 2 -> n 64

    const int rowA = lane & 15, kqA = lane >> 4;
    const int rowB = (lane & 7) + ((lane >> 4) << 3);
    const int kqB = (lane >> 3) & 1;
    const uint32_t xorA = (uint32_t)((rowA & 7) << 4);
    const uint32_t xorB = (uint32_t)((rowB & 7) << 4);
    uint32_t rbyteA[4], rbyteB[4];
#pragma unroll
    for (int im = 0; im < 4; im++)
        rbyteA[im] = (uint32_t)((warp_m * 64 + im * 16 + rowA) * 128);
#pragma unroll
    for (int ib = 0; ib < 4; ib++)
        rbyteB[ib] = (uint32_t)((warp_n * 64 + ib * 16 + rowB) * 128);

    float acc[4][8][4];
#pragma unroll
    for (int im = 0; im < 4; im++)
#pragma unroll
        for (int in = 0; in < 8; in++)
#pragma unroll
            for (int q = 0; q < 4; q++) acc[im][in][q] = 0.0f;

    // prologue: stages 0,1
    load_stage(sb, m0, n0, 0, tid); cp_commit();
    load_stage(sb + STG_B, m0, n0, KC, tid); cp_commit();

    for (int c = 0; c < NCHUNK; c++) {
        cp_wait1();
        __syncthreads();
        const uint32_t baseA = sb + (c % NSTG) * STG_B;
        const uint32_t baseB = baseA + TILE_B;
#pragma unroll
        for (int kk = 0; kk < 4; kk++) {
            const uint32_t offA = ((uint32_t)(kk * 32 + kqA * 16)) ^ xorA;
            const uint32_t offB = ((uint32_t)(kk * 32 + kqB * 16)) ^ xorB;
            uint32_t ra[4][4], rb[4][4];
#pragma unroll
            for (int im = 0; im < 4; im++) ldsm4(ra[im], baseA + rbyteA[im] + offA);
#pragma unroll
            for (int ib = 0; ib < 4; ib++) ldsm4(rb[ib], baseB + rbyteB[ib] + offB);
#pragma unroll
            for (int im = 0; im < 4; im++)
#pragma unroll
                for (int in = 0; in < 8; in++)
                    mma16816(acc[im][in], ra[im], rb[in >> 1][(in & 1) * 2], rb[in >> 1][(in & 1) * 2 + 1]);
        }
        __syncthreads();
        if (c + 2 < NCHUNK) {
            load_stage(sb + ((c + 2) % NSTG) * STG_B, m0, n0, (c + 2) * KC, tid);
        }
        cp_commit();
    }

    // epilogue: bias + (sigmoid), store fp16 -> g_zb / g_hb
    const bool zt = (nt < 8);
    const float* bias = zt ? bz : bh;
    __half* buf = zt ? g_zb : g_hb;
    const int nbase = n0 - (zt ? 0 : 1024);

#pragma unroll
    for (int in = 0; in < 8; in++) {
        const int col = nbase + warp_n * 64 + in * 8 + (lane & 3) * 2;  // even
        const float b0 = __ldg(&bias[col]);
        const float b1 = __ldg(&bias[col + 1]);
#pragma unroll
        for (int im = 0; im < 4; im++) {
            const int row = m0 + warp_m * 64 + im * 16 + (lane >> 2);
            float v0 = acc[im][in][0] + b0;
            float v1 = acc[im][in][1] + b1;
            float v2 = acc[im][in][2] + b0;
            float v3 = acc[im][in][3] + b1;
            if (zt) {
                v0 = 1.0f / (1.0f + __expf(-v0));
                v1 = 1.0f / (1.0f + __expf(-v1));
                v2 = 1.0f / (1.0f + __expf(-v2));
                v3 = 1.0f / (1.0f + __expf(-v3));
            }
            *(__half2*)(buf + (size_t)row * H_DIM + col) =
                __halves2half2(__float2half_rn(v0), __float2half_rn(v1));
            *(__half2*)(buf + (size_t)(row + 8) * H_DIM + col) =
                __halves2half2(__float2half_rn(v2), __float2half_rn(v3));
        }
    }
}

// ---------------- scan: segment summaries then replay ------------------------
__global__ void scan_sum_k() {
    const int idx = blockIdx.x * blockDim.x + threadIdx.x;  // (SEG-1)*8192
    const int seg = idx >> 13;            // 0..14
    const int pr = idx & 8191;
    const int lane0 = pr * 2;
    const int b = lane0 >> 10;
    const int h = lane0 & 1023;
    const size_t base = ((size_t)b * T_DIM + seg * SEGLEN) * H_DIM + h;
    const __half* zp = g_zb + base;
    const __half* hp = g_hb + base;
    float P0 = 1.0f, Q0 = 0.0f, P1 = 1.0f, Q1 = 0.0f;
#pragma unroll 8
    for (int t = 0; t < SEGLEN; t++) {
        const float2 z = __half22float2(*(const __half2*)(zp + (size_t)t * H_DIM));
        const float2 ht = __half22float2(*(const __half2*)(hp + (size_t)t * H_DIM));
        const float a0 = 1.0f - z.x, a1 = 1.0f - z.y;
        P0 *= a0; Q0 = fmaf(a0, Q0, z.x * ht.x);
        P1 *= a1; Q1 = fmaf(a1, Q1, z.y * ht.y);
    }
    *(float2*)&g_P[seg][lane0] = make_float2(P0, P1);
    *(float2*)&g_Q[seg][lane0] = make_float2(Q0, Q1);
}

__global__ void scan_final_k(const float* __restrict__ h0, float* __restrict__ out) {
    const int idx = blockIdx.x * blockDim.x + threadIdx.x;  // SEG*8192
    const int seg = idx >> 13;            // 0..15
    const int pr = idx & 8191;
    const int lane0 = pr * 2;
    const int b = lane0 >> 10;
    const int h = lane0 & 1023;
    float2 hh = *(const float2*)(h0 + lane0);
    for (int s = 0; s < seg; s++) {
        const float2 P = *(const float2*)&g_P[s][lane0];
        const float2 Q = *(const float2*)&g_Q[s][lane0];
        hh.x = fmaf(P.x, hh.x, Q.x);
        hh.y = fmaf(P.y, hh.y, Q.y);
    }
    const size_t base = ((size_t)b * T_DIM + seg * SEGLEN) * H_DIM + h;
    const __half* zp = g_zb + base;
    const __half* hp = g_hb + base;
    float* op = out + base;
#pragma unroll 8
    for (int t = 0; t < SEGLEN; t++) {
        const float2 z = __half22float2(*(const __half2*)(zp + (size_t)t * H_DIM));
        const float2 ht = __half22float2(*(const __half2*)(hp + (size_t)t * H_DIM));
        hh.x = fmaf(z.x, ht.x - hh.x, hh.x);
        hh.y = fmaf(z.y, ht.y - hh.y, hh.y);
        *(float2*)(op + (size_t)t * H_DIM) = hh;
    }
}

// ---------------- launch -----------------------------------------------------
extern "C" void kernel_launch(void* const* d_in, const int* in_sizes, int n_in,
                              void* d_out, int out_size) {
    const float* x  = (const float*)d_in[0];
    const float* h0 = (const float*)d_in[1];
    const float* Wz = (const float*)d_in[2];
    const float* bz = (const float*)d_in[3];
    const float* Wh = (const float*)d_in[4];
    const float* bh = (const float*)d_in[5];
    float* out = (float*)d_out;

    cudaFuncSetAttribute(gemm_k, cudaFuncAttributeMaxDynamicSharedMemorySize, SMEM_TOTAL);

    conv_x_k<<<16384, 256>>>(x);
    conv_w_k<<<1024, 256>>>(Wz, Wh);
    // n fastest: CTAs sharing an X m-tile run concurrently; A+B L2-resident
    gemm_k<<<dim3(16, 256, 1), 128, SMEM_TOTAL>>>(bz, bh);
    scan_sum_k<<<480, 256>>>();
    scan_final_k<<<512, 256>>>(h0, out);
}

// round 16
// speedup vs baseline: 1.2056x; 1.0678x over previous
#include <cuda_runtime.h>
#include <cuda_fp16.h>
#include <cstdint>
#include <cstddef>

// ---------------------------------------------------------------------------
// MinGRU: single-pass fp16 GEMM (mma.sync.m16n8k16), R11 shape (8 warps of
// 64x32, 256 thr, 3-stage, 2 CTA/SM -- best measured) with a reordered
// single-barrier mainloop: wait -> sync -> issue next loads -> compute.
// Removes 1 of 2 barriers per chunk and issues cp.async a whole compute
// block earlier (R8-vs-R11 algebra: chunk overhead ~0.37x compute).
// fp16 z/h~ intermediates + segmented affine scan (all measured).
// ---------------------------------------------------------------------------

#define B_DIM 16
#define T_DIM 2048
#define D_DIM 1024
#define H_DIM 1024
#define M_TOT (B_DIM * T_DIM)   // 32768
#define N_TOT (2 * H_DIM)       // 2048
#define K_TOT D_DIM             // 1024

#define KC      64              // K elems per stage (128B fp16 rows)
#define NSTG    3
#define NCHUNK  (K_TOT / KC)    // 16
#define TILE_B  (128 * 128)     // 16KB
#define STG_B   (2 * TILE_B)    // A + B = 32KB
#define SMEM_TOTAL (NSTG * STG_B)  // 98304 -> 2 CTAs/SM

#define SEG     16              // scan segments
#define SEGLEN  (T_DIM / SEG)   // 128
#define NLANES  (B_DIM * H_DIM) // 16384

// ---------------- scratch (static device memory; no allocation) -------------
__device__ __align__(256) __half g_xh[(size_t)M_TOT * K_TOT];   // 64MB
__device__ __align__(256) __half g_wh[(size_t)N_TOT * K_TOT];   // 4MB
__device__ __align__(256) __half g_zb[(size_t)M_TOT * H_DIM];   // gates (fp16)
__device__ __align__(256) __half g_hb[(size_t)M_TOT * H_DIM];   // cands (fp16)
__device__ __align__(256) float g_P[SEG][NLANES];               // seg prod
__device__ __align__(256) float g_Q[SEG][NLANES];               // seg offset

// ---------------- PTX helpers ----------------------------------------------
__device__ __forceinline__ uint32_t s2u(const void* p) {
    return (uint32_t)__cvta_generic_to_shared(p);
}
__device__ __forceinline__ void cp_async16(uint32_t dst, const void* src) {
    asm volatile("cp.async.cg.shared.global [%0], [%1], 16;" :: "r"(dst), "l"(src) : "memory");
}
__device__ __forceinline__ void cp_commit() {
    asm volatile("cp.async.commit_group;" ::: "memory");
}
__device__ __forceinline__ void cp_wait1() {
    asm volatile("cp.async.wait_group 1;" ::: "memory");
}
__device__ __forceinline__ void ldsm4(uint32_t* r, uint32_t addr) {
    asm volatile("ldmatrix.sync.aligned.m8n8.x4.shared.b16 {%0,%1,%2,%3}, [%4];"
                 : "=r"(r[0]), "=r"(r[1]), "=r"(r[2]), "=r"(r[3]) : "r"(addr));
}
__device__ __forceinline__ void mma16816(float* d, const uint32_t* a, uint32_t b0, uint32_t b1) {
    asm volatile("mma.sync.aligned.m16n8k16.row.col.f32.f16.f16.f32 "
                 "{%0,%1,%2,%3}, {%4,%5,%6,%7}, {%8,%9}, {%0,%1,%2,%3};"
                 : "+f"(d[0]), "+f"(d[1]), "+f"(d[2]), "+f"(d[3])
                 : "r"(a[0]), "r"(a[1]), "r"(a[2]), "r"(a[3]), "r"(b0), "r"(b1));
}

// ---------------- combined convert kernel ------------------------------------
// blocks [0, 16384): x -> fp16;  blocks [16384, 17408): Wz|Wh -> fp16
__global__ void conv_all_k(const float* __restrict__ x,
                           const float* __restrict__ Wz,
                           const float* __restrict__ Wh) {
    if (blockIdx.x < 16384) {
        size_t i = (size_t)blockIdx.x * blockDim.x + threadIdx.x;
        size_t e = i * 8;
        const float4* src = (const float4*)(x + e);
        float4 a = src[0], b = src[1];
        float f[8] = {a.x, a.y, a.z, a.w, b.x, b.y, b.z, b.w};
        union { __half h[8]; uint4 u; } H;
#pragma unroll
        for (int j = 0; j < 8; j++) H.h[j] = __float2half_rn(f[j]);
        ((uint4*)g_xh)[i] = H.u;
    } else {
        size_t i = (size_t)(blockIdx.x - 16384) * blockDim.x + threadIdx.x;
        size_t e = i * 8;
        int row = (int)(e >> 10);
        int k = (int)(e & 1023);
        const float* srcp = (row < H_DIM) ? (Wz + (size_t)row * D_DIM + k)
                                          : (Wh + (size_t)(row - H_DIM) * D_DIM + k);
        float4 a = ((const float4*)srcp)[0], b = ((const float4*)srcp)[1];
        float f[8] = {a.x, a.y, a.z, a.w, b.x, b.y, b.z, b.w};
        union { __half h[8]; uint4 u; } H;
#pragma unroll
        for (int j = 0; j < 8; j++) H.h[j] = __float2half_rn(f[j]);
        ((uint4*)g_wh)[i] = H.u;
    }
}

// ---------------- GEMM ------------------------------------------------------
__device__ __forceinline__ void load_stage(uint32_t dst, int m0, int n0, int k0, int tid) {
    const char* pA = (const char*)(g_xh + (size_t)m0 * K_TOT + k0);
    const char* pB = (const char*)(g_wh + (size_t)n0 * K_TOT + k0);
#pragma unroll
    for (int i = 0; i < 4; i++) {
        int gid = i * 256 + tid;       // 0..1023
        int r = gid >> 3;              // row 0..127
        int cb = gid & 7;              // 16B granule
        uint32_t bo = (uint32_t)(r * 128 + cb * 16);
        uint32_t sw = bo ^ ((bo >> 3) & 0x70);
        size_t goff = (size_t)r * (K_TOT * 2) + cb * 16;
        cp_async16(dst + sw,          pA + goff);
        cp_async16(dst + TILE_B + sw, pB + goff);
    }
}

__global__ void __launch_bounds__(256, 2)
gemm_k(const float* __restrict__ bz, const float* __restrict__ bh) {
    extern __shared__ __align__(1024) char smem[];
    const uint32_t sb = s2u(smem);
    const int tid = threadIdx.x;
    const int wid = tid >> 5, lane = tid & 31;
    const int nt = blockIdx.x;   // 0..15
    const int mt = blockIdx.y;   // 0..255
    const int m0 = mt * 128, n0 = nt * 128;

    const int warp_m = wid & 1;  // 2
    const int warp_n = wid >> 1; // 4

    const int rowA = lane & 15, kqA = lane >> 4;
    const int rowB = (lane & 7) + ((lane >> 4) << 3);
    const int kqB = (lane >> 3) & 1;
    const uint32_t xorA = (uint32_t)((rowA & 7) << 4);
    const uint32_t xorB = (uint32_t)((rowB & 7) << 4);
    uint32_t rbyteA[4], rbyteB[2];
#pragma unroll
    for (int im = 0; im < 4; im++)
        rbyteA[im] = (uint32_t)((warp_m * 64 + im * 16 + rowA) * 128);
#pragma unroll
    for (int ib = 0; ib < 2; ib++)
        rbyteB[ib] = (uint32_t)((warp_n * 32 + ib * 16 + rowB) * 128);

    float acc[4][4][4];
#pragma unroll
    for (int im = 0; im < 4; im++)
#pragma unroll
        for (int in = 0; in < 4; in++)
#pragma unroll
            for (int q = 0; q < 4; q++) acc[im][in][q] = 0.0f;

    // prologue: stages 0,1
    load_stage(sb, m0, n0, 0, tid); cp_commit();
    load_stage(sb + STG_B, m0, n0, KC, tid); cp_commit();

    for (int c = 0; c < NCHUNK; c++) {
        cp_wait1();                       // stage c resident (group c complete)
        __syncthreads();                  // all warps done compute(c-1): safe to
                                          // overwrite stage (c+2)%3 == (c-1)%3
        if (c + 2 < NCHUNK)
            load_stage(sb + ((c + 2) % NSTG) * STG_B, m0, n0, (c + 2) * KC, tid);
        cp_commit();                      // group c+2 (possibly empty)

        const uint32_t baseA = sb + (c % NSTG) * STG_B;
        const uint32_t baseB = baseA + TILE_B;
#pragma unroll
        for (int kk = 0; kk < 4; kk++) {
            const uint32_t offA = ((uint32_t)(kk * 32 + kqA * 16)) ^ xorA;
            const uint32_t offB = ((uint32_t)(kk * 32 + kqB * 16)) ^ xorB;
            uint32_t ra[4][4], rb[2][4];
#pragma unroll
            for (int im = 0; im < 4; im++) ldsm4(ra[im], baseA + rbyteA[im] + offA);
#pragma unroll
            for (int ib = 0; ib < 2; ib++) ldsm4(rb[ib], baseB + rbyteB[ib] + offB);
#pragma unroll
            for (int im = 0; im < 4; im++)
#pragma unroll
                for (int in = 0; in < 4; in++)
                    mma16816(acc[im][in], ra[im], rb[in >> 1][(in & 1) * 2], rb[in >> 1][(in & 1) * 2 + 1]);
        }
    }

    // epilogue: bias + (sigmoid), store fp16 -> g_zb / g_hb
    const bool zt = (nt < 8);
    const float* bias = zt ? bz : bh;
    __half* buf = zt ? g_zb : g_hb;
    const int nbase = n0 - (zt ? 0 : 1024);

#pragma unroll
    for (int in = 0; in < 4; in++) {
        const int col = nbase + warp_n * 32 + in * 8 + (lane & 3) * 2;  // even
        const float b0 = __ldg(&bias[col]);
        const float b1 = __ldg(&bias[col + 1]);
#pragma unroll
        for (int im = 0; im < 4; im++) {
            const int row = m0 + warp_m * 64 + im * 16 + (lane >> 2);
            float v0 = acc[im][in][0] + b0;
            float v1 = acc[im][in][1] + b1;
            float v2 = acc[im][in][2] + b0;
            float v3 = acc[im][in][3] + b1;
            if (zt) {
                v0 = 1.0f / (1.0f + __expf(-v0));
                v1 = 1.0f / (1.0f + __expf(-v1));
                v2 = 1.0f / (1.0f + __expf(-v2));
                v3 = 1.0f / (1.0f + __expf(-v3));
            }
            *(__half2*)(buf + (size_t)row * H_DIM + col) =
                __halves2half2(__float2half_rn(v0), __float2half_rn(v1));
            *(__half2*)(buf + (size_t)(row + 8) * H_DIM + col) =
                __halves2half2(__float2half_rn(v2), __float2half_rn(v3));
        }
    }
}

// ---------------- scan: segment summaries then replay ------------------------
__global__ void scan_sum_k() {
    const int idx = blockIdx.x * blockDim.x + threadIdx.x;  // (SEG-1)*8192
    const int seg = idx >> 13;            // 0..14
    const int pr = idx & 8191;
    const int lane0 = pr * 2;
    const int b = lane0 >> 10;
    const int h = lane0 & 1023;
    const size_t base = ((size_t)b * T_DIM + seg * SEGLEN) * H_DIM + h;
    const __half* zp = g_zb + base;
    const __half* hp = g_hb + base;
    float P0 = 1.0f, Q0 = 0.0f, P1 = 1.0f, Q1 = 0.0f;
#pragma unroll 8
    for (int t = 0; t < SEGLEN; t++) {
        const float2 z = __half22float2(*(const __half2*)(zp + (size_t)t * H_DIM));
        const float2 ht = __half22float2(*(const __half2*)(hp + (size_t)t * H_DIM));
        const float a0 = 1.0f - z.x, a1 = 1.0f - z.y;
        P0 *= a0; Q0 = fmaf(a0, Q0, z.x * ht.x);
        P1 *= a1; Q1 = fmaf(a1, Q1, z.y * ht.y);
    }
    *(float2*)&g_P[seg][lane0] = make_float2(P0, P1);
    *(float2*)&g_Q[seg][lane0] = make_float2(Q0, Q1);
}

__global__ void scan_final_k(const float* __restrict__ h0, float* __restrict__ out) {
    const int idx = blockIdx.x * blockDim.x + threadIdx.x;  // SEG*8192
    const int seg = idx >> 13;            // 0..15
    const int pr = idx & 8191;
    const int lane0 = pr * 2;
    const int b = lane0 >> 10;
    const int h = lane0 & 1023;
    float2 hh = *(const float2*)(h0 + lane0);
    for (int s = 0; s < seg; s++) {
        const float2 P = *(const float2*)&g_P[s][lane0];
        const float2 Q = *(const float2*)&g_Q[s][lane0];
        hh.x = fmaf(P.x, hh.x, Q.x);
        hh.y = fmaf(P.y, hh.y, Q.y);
    }
    const size_t base = ((size_t)b * T_DIM + seg * SEGLEN) * H_DIM + h;
    const __half* zp = g_zb + base;
    const __half* hp = g_hb + base;
    float* op = out + base;
#pragma unroll 8
    for (int t = 0; t < SEGLEN; t++) {
        const float2 z = __half22float2(*(const __half2*)(zp + (size_t)t * H_DIM));
        const float2 ht = __half22float2(*(const __half2*)(hp + (size_t)t * H_DIM));
        hh.x = fmaf(z.x, ht.x - hh.x, hh.x);
        hh.y = fmaf(z.y, ht.y - hh.y, hh.y);
        *(float2*)(op + (size_t)t * H_DIM) = hh;
    }
}

// ---------------- launch -----------------------------------------------------
extern "C" void kernel_launch(void* const* d_in, const int* in_sizes, int n_in,
                              void* d_out, int out_size) {
    const float* x  = (const float*)d_in[0];
    const float* h0 = (const float*)d_in[1];
    const float* Wz = (const float*)d_in[2];
    const float* bz = (const float*)d_in[3];
    const float* Wh = (const float*)d_in[4];
    const float* bh = (const float*)d_in[5];
    float* out = (float*)d_out;

    cudaFuncSetAttribute(gemm_k, cudaFuncAttributeMaxDynamicSharedMemorySize, SMEM_TOTAL);

    conv_all_k<<<17408, 256>>>(x, Wz, Wh);
    // n fastest: CTAs sharing an X m-tile run concurrently; A+B L2-resident
    gemm_k<<<dim3(16, 256, 1), 256, SMEM_TOTAL>>>(bz, bh);
    scan_sum_k<<<480, 256>>>();
    scan_final_k<<<512, 256>>>(h0, out);
}